// round 15
// baseline (speedup 1.0000x reference)
#include <cuda_runtime.h>
#include <math.h>
#include <stdint.h>

#define Bsz 32
#define Ssz 2048
#define Isz 256
#define Hsz 256
#define Msz 1024   // 4*H, packed as m = j*4 + g  (g: 0=f,1=i,2=c,3=o)

typedef unsigned long long ull;

// ------------------------------- f32x2 helpers ---------------------------------
__device__ __forceinline__ ull pack2(float lo, float hi) {
    ull r; asm("mov.b64 %0, {%1,%2};" : "=l"(r) : "f"(lo), "f"(hi)); return r;
}
__device__ __forceinline__ void unpack2(float& lo, float& hi, ull v) {
    asm("mov.b64 {%0,%1}, %2;" : "=f"(lo), "=f"(hi) : "l"(v));
}
__device__ __forceinline__ void fma2(ull& d, ull a, ull b) {
    asm("fma.rn.f32x2 %0, %1, %2, %0;" : "+l"(d) : "l"(a), "l"(b));
}
__device__ __forceinline__ ull add2(ull a, ull b) {
    ull r; asm("add.rn.f32x2 %0, %1, %2;" : "=l"(r) : "l"(a), "l"(b)); return r;
}

// ------------------------------- mbarrier helpers ------------------------------
__device__ __forceinline__ void mbar_init(unsigned addr, unsigned count) {
    asm volatile("mbarrier.init.shared.b64 [%0], %1;" :: "r"(addr), "r"(count) : "memory");
}
__device__ __forceinline__ void mbar_expect_tx(unsigned addr, unsigned bytes) {
    asm volatile("mbarrier.arrive.expect_tx.shared.b64 _, [%0], %1;"
                 :: "r"(addr), "r"(bytes) : "memory");
}
__device__ __forceinline__ void mbar_wait(unsigned addr, unsigned parity) {
    unsigned done;
    asm volatile(
        "{\n\t.reg .pred p;\n\t"
        "mbarrier.try_wait.parity.acquire.cta.shared::cta.b64 p, [%1], %2;\n\t"
        "selp.b32 %0, 1, 0, p;\n\t}"
        : "=r"(done) : "r"(addr), "r"(parity) : "memory");
    if (!done) {
        asm volatile(
            "{\n\t.reg .pred P1;\n\t"
            "WL_%=:\n\t"
            "mbarrier.try_wait.parity.acquire.cta.shared::cta.b64 P1, [%0], %1, 0x989680;\n\t"
            "@P1 bra.uni WD_%=;\n\t"
            "bra.uni WL_%=;\n\t"
            "WD_%=:\n\t}"
            :: "r"(addr), "r"(parity) : "memory");
    }
}

// ------------------------------- device scratch -------------------------------
__device__ float g_xp[(size_t)Bsz * Ssz * Msz];        // [t][b][m]  (256 MB)

// ------------------------------- xproj GEMM (f32x2, inline pack) ---------------
// xp[r][m] = sum_k x_row(r)[k] * Wall[k+256][m] + b_all[m],  r = t*32 + b,
// m = j*4 + g. W/b gathered directly from the four per-gate arrays. (R12-proven)
#define XBM 128
#define XBN 128
#define XBK 8

__global__ __launch_bounds__(256) void xproj_kernel(
        const float* __restrict__ x,
        const float* __restrict__ Wf, const float* __restrict__ Wi,
        const float* __restrict__ Wc, const float* __restrict__ Wo,
        const float* __restrict__ bf, const float* __restrict__ bi,
        const float* __restrict__ bc, const float* __restrict__ bo) {
    __shared__ float As[XBK][XBM + 4];
    __shared__ float Bs[XBK][XBN];

    int bn = blockIdx.x;               // 0..7    (m blocks)
    int bm = blockIdx.y;               // 0..511  (row blocks)
    int tid = threadIdx.x;
    int tx = tid & 15;
    int ty = tid >> 4;

    int r0 = bm * XBM;
    int m0 = bn * XBN;

    int arow = tid >> 1, akq = tid & 1;
    int r = r0 + arow;
    int b = r & 31, t = r >> 5;
    const float* arow_ptr = x + ((size_t)b * Ssz + t) * Isz;

    int bk = tid >> 5, bmq = tid & 31;          // B tile: k row bk, j = bn*32+bmq
    int jb = bn * 32 + bmq;

    ull acc2[8][4];
    #pragma unroll
    for (int i = 0; i < 8; i++)
        #pragma unroll
        for (int jp = 0; jp < 4; jp++) acc2[i][jp] = 0ull;

    for (int k0 = 0; k0 < Isz; k0 += XBK) {
        float4 av = *(const float4*)(arow_ptr + k0 + akq * 4);
        As[akq * 4 + 0][arow] = av.x;
        As[akq * 4 + 1][arow] = av.y;
        As[akq * 4 + 2][arow] = av.z;
        As[akq * 4 + 3][arow] = av.w;
        {
            size_t off = (size_t)(k0 + bk + 256) * Hsz + jb;
            float4 wv;
            wv.x = Wf[off]; wv.y = Wi[off]; wv.z = Wc[off]; wv.w = Wo[off];
            *(float4*)&Bs[bk][bmq * 4] = wv;
        }
        __syncthreads();
        #pragma unroll
        for (int kk = 0; kk < XBK; kk++) {
            float4 aA = *(float4*)&As[kk][ty * 8];
            float4 aB = *(float4*)&As[kk][ty * 8 + 4];
            ulonglong2 bL = *(ulonglong2*)&Bs[kk][tx * 8];
            ulonglong2 bH = *(ulonglong2*)&Bs[kk][tx * 8 + 4];
            ull b2[4] = {bL.x, bL.y, bH.x, bH.y};
            float ar[8] = {aA.x, aA.y, aA.z, aA.w, aB.x, aB.y, aB.z, aB.w};
            #pragma unroll
            for (int i = 0; i < 8; i++) {
                ull a2 = pack2(ar[i], ar[i]);
                #pragma unroll
                for (int jp = 0; jp < 4; jp++) fma2(acc2[i][jp], a2, b2[jp]);
            }
        }
        __syncthreads();
    }

    ull bias2[4];
    {
        int j0 = bn * 32 + tx * 2;
        bias2[0] = pack2(bf[j0], bi[j0]);
        bias2[1] = pack2(bc[j0], bo[j0]);
        bias2[2] = pack2(bf[j0 + 1], bi[j0 + 1]);
        bias2[3] = pack2(bc[j0 + 1], bo[j0 + 1]);
    }
    #pragma unroll
    for (int i = 0; i < 8; i++) {
        int rr = r0 + ty * 8 + i;
        float* dst = g_xp + (size_t)rr * Msz + m0 + tx * 8;
        ulonglong2 oL, oH;
        oL.x = add2(acc2[i][0], bias2[0]);
        oL.y = add2(acc2[i][1], bias2[1]);
        oH.x = add2(acc2[i][2], bias2[2]);
        oH.y = add2(acc2[i][3], bias2[3]);
        *(ulonglong2*)dst = oL;
        *(ulonglong2*)(dst + 4) = oH;
    }
}

// ------------------------------- clustered recurrence --------------------------
// 16 clusters x 8 CTAs x 256 threads. R10's proven protocol (4B st.async +
// expect_tx full barriers, count-8 empty barriers, 4-deep ring, strided-k
// register weights), but the cluster's TWO batches are now INDEPENDENT CHAINS
// with separate buffers/barriers, processed back-to-back each step:
// waitA/gemmA/sendA then waitB/gemmB/sendB. Chain A's fabric+straggler latency
// is overlapped by chain B's compute (and vice versa across the step boundary).
// Per chain: 16-value butterfly (lane L -> value L>>1), owners lane&7==0.
__global__ __launch_bounds__(256, 1) __cluster_dims__(8, 1, 1)
void lstm_rec(const float* __restrict__ h0, const float* __restrict__ c0,
              const float* __restrict__ Wf, const float* __restrict__ Wi,
              const float* __restrict__ Wc, const float* __restrict__ Wo,
              float* __restrict__ out, int write_finals) {
    __shared__ __align__(16) float h_s[2][4][Hsz];      // [chain][buf][j]
    __shared__ __align__(8) ull mbar[16];               // full[c][p] (8), empty[c][p] (8)
    __shared__ unsigned s_rh[8], s_rmb[8];              // remote bases per rank

    int tid = threadIdx.x;
    int clu = blockIdx.x >> 3;
    int w = tid >> 5;
    int lane = tid & 31;
    unsigned rank;
    asm("mov.u32 %0, %%cluster_ctarank;" : "=r"(rank));

    unsigned my_hs = (unsigned)__cvta_generic_to_shared(h_s);
    unsigned my_mb = (unsigned)__cvta_generic_to_shared(mbar);
    // full[c][p]  at my_mb + (c*4+p)*8
    // empty[c][p] at my_mb + 64 + (c*4+p)*8

    if (tid == 0) {
        #pragma unroll
        for (int c = 0; c < 2; c++)
            #pragma unroll
            for (int p = 0; p < 4; p++) {
                mbar_init(my_mb + (c * 4 + p) * 8, 1);        // full
                mbar_init(my_mb + 64 + (c * 4 + p) * 8, 8);   // empty
            }
        // pre-arm full[c][1..3] (stores of steps 0,1,2); buf0 re-armed at t=0 tail
        #pragma unroll
        for (int c = 0; c < 2; c++)
            #pragma unroll
            for (int p = 1; p < 4; p++)
                mbar_expect_tx(my_mb + (c * 4 + p) * 8, 1024);
    }
    if (tid < 8) {
        unsigned a;
        asm("mapa.shared::cluster.u32 %0, %1, %2;" : "=r"(a) : "r"(my_hs), "r"(tid));
        s_rh[tid] = a;
        asm("mapa.shared::cluster.u32 %0, %1, %2;" : "=r"(a) : "r"(my_mb), "r"(tid));
        s_rmb[tid] = a;
    }

    int jg0 = (int)rank * 32 + w * 4;   // first of this warp's FOUR global j's

    // weights (inline gather, R12-proven), k-pair packed over strided k:
    // wkp[p][jj*4+g] = (W_g[(lane+64p)*256 + j], W_g[(lane+64p+32)*256 + j])
    ull wkp[4][16];
    {
        const float* Wg[4] = {Wf, Wi, Wc, Wo};
        #pragma unroll
        for (int p = 0; p < 4; p++) {
            int kA = lane + 64 * p, kB = kA + 32;
            #pragma unroll
            for (int jj = 0; jj < 4; jj++) {
                int j = jg0 + jj;
                #pragma unroll
                for (int g = 0; g < 4; g++)
                    wkp[p][jj * 4 + g] = pack2(Wg[g][(size_t)kA * Hsz + j],
                                               Wg[g][(size_t)kB * Hsz + j]);
            }
        }
    }

    // 16-value butterfly lane mapping: lane L ends with value v = L>>1,
    // v = jj*4 + g  ->  jj_x = L>>3, g_x = (L>>1)&3. Owner lanes: lane&7==0.
    int jj_x = lane >> 3;
    int g_x = (lane >> 1) & 3;
    int jg_x = jg0 + jj_x;
    bool owner = ((lane & 7) == 0);     // one per jj: lanes 0,8,16,24
    int bgA = clu * 2, bgB = clu * 2 + 1;

    // init h0 into buf 0 of both chains
    h_s[0][0][tid] = h0[bgA * Hsz + tid];
    h_s[1][0][tid] = h0[bgB * Hsz + tid];

    float cA = owner ? c0[bgA * Hsz + jg_x] : 0.f;
    float cB = owner ? c0[bgB * Hsz + jg_x] : 0.f;

    const float* xpA = g_xp + (size_t)bgA * Msz + jg_x * 4 + g_x;
    const float* xpB = g_xp + (size_t)bgB * Msz + jg_x * 4 + g_x;
    float xvA = xpA[0], xvB = xpB[0];    // t=0

    float* outA = out + (size_t)bgA * Ssz * Hsz + jg_x;
    float* outB = out + (size_t)bgB * Ssz * Hsz + jg_x;
    const size_t fin_off = (size_t)Bsz * Ssz * Hsz;

    __syncthreads();
    asm volatile("barrier.cluster.arrive.aligned;" ::: "memory");
    asm volatile("barrier.cluster.wait.aligned;" ::: "memory");

    for (int t = 0; t < Ssz; t++) {
        int cur = t & 3, nb = (t + 1) & 3;
        bool not_last = (t + 1 < Ssz);
        unsigned par_full = ((unsigned)(t - 1) >> 2) & 1u;
        unsigned par_empty = ((unsigned)(t - 3) >> 2) & 1u;

        float hnA = 0.f, hnB = 0.f;

        #pragma unroll
        for (int c = 0; c < 2; c++) {
            // ---- chain c: wait, gemm, reduce, act, send ----
            if (t) mbar_wait(my_mb + (c * 4 + cur) * 8, par_full);

            const float* hb = &h_s[c][cur][0];
            float hv[8];
            #pragma unroll
            for (int i = 0; i < 8; i++) hv[i] = hb[lane + 32 * i];
            ull hp[4];
            #pragma unroll
            for (int p = 0; p < 4; p++) hp[p] = pack2(hv[2 * p], hv[2 * p + 1]);

            ull acc2[16];
            #pragma unroll
            for (int m = 0; m < 16; m++) acc2[m] = 0ull;
            #pragma unroll
            for (int p = 0; p < 4; p++)
                #pragma unroll
                for (int m = 0; m < 16; m++) fma2(acc2[m], wkp[p][m], hp[p]);

            float acc[16];
            #pragma unroll
            for (int m = 0; m < 16; m++) {
                float lo, hi; unpack2(lo, hi, acc2[m]);
                acc[m] = lo + hi;
            }

            // 16-value butterfly over 32 lanes: lane L ends with value L>>1
            int cnt = 16;
            #pragma unroll
            for (int off = 16; off >= 2; off >>= 1) {
                cnt >>= 1;
                bool upper = (lane & off) != 0;
                #pragma unroll
                for (int v = 0; v < cnt; v++) {
                    float send = upper ? acc[v] : acc[v + cnt];
                    float recv = __shfl_xor_sync(0xffffffffu, send, off);
                    acc[v] = (upper ? acc[v + cnt] : acc[v]) + recv;
                }
            }
            acc[0] += __shfl_xor_sync(0xffffffffu, acc[0], 1);

            float pre = acc[0] + (c == 0 ? xvA : xvB);
            float a;
            if (g_x == 2) { float e = __expf(-2.f * pre); a = __fdividef(2.f, 1.f + e) - 1.f; }
            else          { a = __fdividef(1.f, 1.f + __expf(-pre)); }

            int base = lane & ~7;
            float fg = __shfl_sync(0xffffffffu, a, base);
            float ig = __shfl_sync(0xffffffffu, a, base + 2);
            float cg = __shfl_sync(0xffffffffu, a, base + 4);
            float og = __shfl_sync(0xffffffffu, a, base + 6);

            if (owner) {
                float& c_val = (c == 0) ? cA : cB;
                c_val = c_val * fg + ig * cg;
                float e = __expf(-2.f * c_val);
                float hn = og * (__fdividef(2.f, 1.f + e) - 1.f);
                if (c == 0) hnA = hn; else hnB = hn;

                if (not_last) {
                    // empty[c][nb] released by readers at t-3 (wait is cheap fast-path)
                    // NOTE: wait executed by all lanes below, before sends
                }
            }

            if (not_last) {
                if (t >= 3) mbar_wait(my_mb + 64 + (c * 4 + nb) * 8, par_empty);
                if (owner) {
                    float hn = (c == 0) ? hnA : hnB;
                    unsigned off4 = (unsigned)(c * 4096 + nb * 1024 + jg_x * 4);
                    unsigned hbits = __float_as_uint(hn);
                    #pragma unroll
                    for (int r = 0; r < 8; r++)
                        asm volatile(
                            "st.async.weak.shared::cluster.mbarrier::complete_tx::bytes.b32 [%0], %1, [%2];"
                            :: "r"(s_rh[r] + off4), "r"(hbits),
                               "r"(s_rmb[r] + (unsigned)(c * 4 + nb) * 8u) : "memory");
                }
            }
        }

        // prefetch next xp (overlaps tail + next waits)
        if (not_last) {
            xvA = __ldg(xpA + (size_t)(t + 1) * Bsz * Msz);
            xvB = __ldg(xpB + (size_t)(t + 1) * Bsz * Msz);
        }

        __syncthreads();   // all warps done reading buf[cur] of BOTH chains

        if (tid == 0) {
            #pragma unroll
            for (int c = 0; c < 2; c++) {
                mbar_expect_tx(my_mb + (c * 4 + cur) * 8, 1024);   // re-arm (reuse t+4)
                #pragma unroll
                for (int r = 0; r < 8; r++)
                    asm volatile("mbarrier.arrive.shared::cluster.b64 _, [%0];"
                                 :: "r"(s_rmb[r] + 64u + (unsigned)(c * 4 + cur) * 8u) : "memory");
            }
        }

        // gmem outputs off the critical chain
        if (owner) {
            outA[(size_t)t * Hsz] = hnA;
            outB[(size_t)t * Hsz] = hnB;
            if (!not_last && write_finals) {
                out[fin_off + (size_t)bgA * Hsz + jg_x] = hnA;
                out[fin_off + (size_t)bgB * Hsz + jg_x] = hnB;
                out[fin_off + (size_t)Bsz * Hsz + (size_t)bgA * Hsz + jg_x] = cA;
                out[fin_off + (size_t)Bsz * Hsz + (size_t)bgB * Hsz + jg_x] = cB;
            }
        }
    }

    // lifetime safety: no CTA exits while cluster peers may have ops in flight
    asm volatile("barrier.cluster.arrive.aligned;" ::: "memory");
    asm volatile("barrier.cluster.wait.aligned;" ::: "memory");
}

// ------------------------------- launch ----------------------------------------
extern "C" void kernel_launch(void* const* d_in, const int* in_sizes, int n_in,
                              void* d_out, int out_size) {
    const float* x  = (const float*)d_in[0];
    const float* h0 = (const float*)d_in[1];
    const float* c0 = (const float*)d_in[2];
    const float* Wf = (const float*)d_in[3];
    const float* bf = (const float*)d_in[4];
    const float* Wi = (const float*)d_in[5];
    const float* bi = (const float*)d_in[6];
    const float* Wc = (const float*)d_in[7];
    const float* bc = (const float*)d_in[8];
    const float* Wo = (const float*)d_in[9];
    const float* bo = (const float*)d_in[10];
    float* out = (float*)d_out;

    int full = Bsz * Ssz * Hsz + 2 * Bsz * Hsz;
    int write_finals = (out_size >= full) ? 1 : 0;

    dim3 grid_x(8, 512);
    xproj_kernel<<<grid_x, 256>>>(x, Wf, Wi, Wc, Wo, bf, bi, bc, bo);

    lstm_rec<<<128, 256>>>(h0, c0, Wf, Wi, Wc, Wo, out, write_finals);
}

// round 16
// speedup vs baseline: 1.6516x; 1.6516x over previous
#include <cuda_runtime.h>
#include <math.h>
#include <stdint.h>

#define Bsz 32
#define Ssz 2048
#define Isz 256
#define Hsz 256
#define Msz 1024   // 4*H, packed as m = j*4 + g  (g: 0=f,1=i,2=c,3=o)

typedef unsigned long long ull;

// ------------------------------- f32x2 helpers ---------------------------------
__device__ __forceinline__ ull pack2(float lo, float hi) {
    ull r; asm("mov.b64 %0, {%1,%2};" : "=l"(r) : "f"(lo), "f"(hi)); return r;
}
__device__ __forceinline__ void unpack2(float& lo, float& hi, ull v) {
    asm("mov.b64 {%0,%1}, %2;" : "=f"(lo), "=f"(hi) : "l"(v));
}
__device__ __forceinline__ void fma2(ull& d, ull a, ull b) {
    asm("fma.rn.f32x2 %0, %1, %2, %0;" : "+l"(d) : "l"(a), "l"(b));
}
__device__ __forceinline__ ull add2(ull a, ull b) {
    ull r; asm("add.rn.f32x2 %0, %1, %2;" : "=l"(r) : "l"(a), "l"(b)); return r;
}

// ------------------------------- mbarrier helpers ------------------------------
__device__ __forceinline__ void mbar_init(unsigned addr, unsigned count) {
    asm volatile("mbarrier.init.shared.b64 [%0], %1;" :: "r"(addr), "r"(count) : "memory");
}
__device__ __forceinline__ void mbar_expect_tx(unsigned addr, unsigned bytes) {
    asm volatile("mbarrier.arrive.expect_tx.shared.b64 _, [%0], %1;"
                 :: "r"(addr), "r"(bytes) : "memory");
}
__device__ __forceinline__ void mbar_wait(unsigned addr, unsigned parity) {
    unsigned done;
    asm volatile(
        "{\n\t.reg .pred p;\n\t"
        "mbarrier.try_wait.parity.acquire.cta.shared::cta.b64 p, [%1], %2;\n\t"
        "selp.b32 %0, 1, 0, p;\n\t}"
        : "=r"(done) : "r"(addr), "r"(parity) : "memory");
    if (!done) {
        asm volatile(
            "{\n\t.reg .pred P1;\n\t"
            "WL_%=:\n\t"
            "mbarrier.try_wait.parity.acquire.cta.shared::cta.b64 P1, [%0], %1, 0x989680;\n\t"
            "@P1 bra.uni WD_%=;\n\t"
            "bra.uni WL_%=;\n\t"
            "WD_%=:\n\t}"
            :: "r"(addr), "r"(parity) : "memory");
    }
}

// ------------------------------- device scratch -------------------------------
__device__ float g_xp[(size_t)Bsz * Ssz * Msz];        // [t][b][m]  (256 MB)

// ------------------------------- xproj GEMM (f32x2, inline pack) ---------------
// xp[r][m] = sum_k x_row(r)[k] * Wall[k+256][m] + b_all[m],  r = t*32 + b,
// m = j*4 + g. W/b gathered directly from the four per-gate arrays. (R12-proven)
#define XBM 128
#define XBN 128
#define XBK 8

__global__ __launch_bounds__(256) void xproj_kernel(
        const float* __restrict__ x,
        const float* __restrict__ Wf, const float* __restrict__ Wi,
        const float* __restrict__ Wc, const float* __restrict__ Wo,
        const float* __restrict__ bf, const float* __restrict__ bi,
        const float* __restrict__ bc, const float* __restrict__ bo) {
    __shared__ float As[XBK][XBM + 4];
    __shared__ float Bs[XBK][XBN];

    int bn = blockIdx.x;               // 0..7    (m blocks)
    int bm = blockIdx.y;               // 0..511  (row blocks)
    int tid = threadIdx.x;
    int tx = tid & 15;
    int ty = tid >> 4;

    int r0 = bm * XBM;
    int m0 = bn * XBN;

    int arow = tid >> 1, akq = tid & 1;
    int r = r0 + arow;
    int b = r & 31, t = r >> 5;
    const float* arow_ptr = x + ((size_t)b * Ssz + t) * Isz;

    int bk = tid >> 5, bmq = tid & 31;          // B tile: k row bk, j = bn*32+bmq
    int jb = bn * 32 + bmq;

    ull acc2[8][4];
    #pragma unroll
    for (int i = 0; i < 8; i++)
        #pragma unroll
        for (int jp = 0; jp < 4; jp++) acc2[i][jp] = 0ull;

    for (int k0 = 0; k0 < Isz; k0 += XBK) {
        float4 av = *(const float4*)(arow_ptr + k0 + akq * 4);
        As[akq * 4 + 0][arow] = av.x;
        As[akq * 4 + 1][arow] = av.y;
        As[akq * 4 + 2][arow] = av.z;
        As[akq * 4 + 3][arow] = av.w;
        {
            size_t off = (size_t)(k0 + bk + 256) * Hsz + jb;
            float4 wv;
            wv.x = Wf[off]; wv.y = Wi[off]; wv.z = Wc[off]; wv.w = Wo[off];
            *(float4*)&Bs[bk][bmq * 4] = wv;
        }
        __syncthreads();
        #pragma unroll
        for (int kk = 0; kk < XBK; kk++) {
            float4 aA = *(float4*)&As[kk][ty * 8];
            float4 aB = *(float4*)&As[kk][ty * 8 + 4];
            ulonglong2 bL = *(ulonglong2*)&Bs[kk][tx * 8];
            ulonglong2 bH = *(ulonglong2*)&Bs[kk][tx * 8 + 4];
            ull b2[4] = {bL.x, bL.y, bH.x, bH.y};
            float ar[8] = {aA.x, aA.y, aA.z, aA.w, aB.x, aB.y, aB.z, aB.w};
            #pragma unroll
            for (int i = 0; i < 8; i++) {
                ull a2 = pack2(ar[i], ar[i]);
                #pragma unroll
                for (int jp = 0; jp < 4; jp++) fma2(acc2[i][jp], a2, b2[jp]);
            }
        }
        __syncthreads();
    }

    ull bias2[4];
    {
        int j0 = bn * 32 + tx * 2;
        bias2[0] = pack2(bf[j0], bi[j0]);
        bias2[1] = pack2(bc[j0], bo[j0]);
        bias2[2] = pack2(bf[j0 + 1], bi[j0 + 1]);
        bias2[3] = pack2(bc[j0 + 1], bo[j0 + 1]);
    }
    #pragma unroll
    for (int i = 0; i < 8; i++) {
        int rr = r0 + ty * 8 + i;
        float* dst = g_xp + (size_t)rr * Msz + m0 + tx * 8;
        ulonglong2 oL, oH;
        oL.x = add2(acc2[i][0], bias2[0]);
        oL.y = add2(acc2[i][1], bias2[1]);
        oH.x = add2(acc2[i][2], bias2[2]);
        oH.y = add2(acc2[i][3], bias2[3]);
        *(ulonglong2*)dst = oL;
        *(ulonglong2*)(dst + 4) = oH;
    }
}

// ------------------------------- clustered recurrence --------------------------
// 16 clusters x 8 CTAs x 256 threads. EXACT R10 protocol minus the empty
// barriers (proven redundant: full-barrier transitivity bounds cluster skew to
// <2 steps, and the ring is 4 deep). Sends spread across each (b,j) quad: lane
// g sends the quad's hn to ranks {2g, 2g+1} (2 st.async.b32 per thread instead
// of 8 per owner). Weights inline-gathered (R12-proven). Everything else —
// layout, GEMM, butterfly, parities, expect_tx=2048 — byte-identical to R10.
__global__ __launch_bounds__(256, 1) __cluster_dims__(8, 1, 1)
void lstm_rec(const float* __restrict__ h0, const float* __restrict__ c0,
              const float* __restrict__ Wf, const float* __restrict__ Wi,
              const float* __restrict__ Wc, const float* __restrict__ Wo,
              float* __restrict__ out, int write_finals) {
    __shared__ __align__(16) float h_s[4][2 * Hsz];     // [buf][b_local*256 + j]
    __shared__ __align__(8) ull mbar[4];                // full[0..3]
    __shared__ unsigned s_rh[8], s_rmb[8];              // remote bases per rank

    int tid = threadIdx.x;
    int clu = blockIdx.x >> 3;
    int w = tid >> 5;
    int lane = tid & 31;
    unsigned rank;
    asm("mov.u32 %0, %%cluster_ctarank;" : "=r"(rank));

    unsigned my_hs = (unsigned)__cvta_generic_to_shared(h_s);
    unsigned my_mb = (unsigned)__cvta_generic_to_shared(mbar);
    // full[p] at my_mb + p*8

    if (tid == 0) {
        #pragma unroll
        for (int p = 0; p < 4; p++) mbar_init(my_mb + p * 8, 1);
        // pre-arm full[1..3] for stores during steps 0,1,2 (buf0 armed in-loop at t=0)
        mbar_expect_tx(my_mb + 8, 2048);
        mbar_expect_tx(my_mb + 16, 2048);
        mbar_expect_tx(my_mb + 24, 2048);
    }
    if (tid < 8) {
        unsigned a;
        asm("mapa.shared::cluster.u32 %0, %1, %2;" : "=r"(a) : "r"(my_hs), "r"(tid));
        s_rh[tid] = a;
        asm("mapa.shared::cluster.u32 %0, %1, %2;" : "=r"(a) : "r"(my_mb), "r"(tid));
        s_rmb[tid] = a;
    }

    int jg0 = (int)rank * 32 + w * 4;   // first of this warp's FOUR global j's

    // weights inline-gathered, k-pair packed over strided k:
    // wkp[p][jj*4+g] = (W_g[(lane+64p)*256 + j], W_g[(lane+64p+32)*256 + j])
    ull wkp[4][16];
    {
        const float* Wg[4] = {Wf, Wi, Wc, Wo};
        #pragma unroll
        for (int p = 0; p < 4; p++) {
            int kA = lane + 64 * p;
            int kB = kA + 32;
            #pragma unroll
            for (int jj = 0; jj < 4; jj++) {
                int j = jg0 + jj;
                #pragma unroll
                for (int g = 0; g < 4; g++)
                    wkp[p][jj * 4 + g] = pack2(Wg[g][(size_t)kA * Hsz + j],
                                               Wg[g][(size_t)kB * Hsz + j]);
            }
        }
    }

    // lane's value id: v = lane = b*16 + jj*4 + g
    int b_me = lane >> 4;
    int jj_me = (lane >> 2) & 3;
    int g_me = lane & 3;
    int jg_me = jg0 + jj_me;
    int bg_me = clu * 2 + b_me;
    bool owner = (g_me == 0);           // 8 owners per warp

    // init h0 into buf 0 (local copy: 2 batches x 256 j), 2 entries per thread
    {
        int i0 = tid, i1 = tid + 256;
        h_s[0][i0] = h0[(clu * 2 + (i0 >> 8)) * Hsz + (i0 & 255)];
        h_s[0][i1] = h0[(clu * 2 + (i1 >> 8)) * Hsz + (i1 & 255)];
    }
    float c_val = owner ? c0[bg_me * Hsz + jg_me] : 0.f;
    float xv = g_xp[(size_t)bg_me * Msz + jg_me * 4 + g_me];   // t=0

    float* out_hj = out + (size_t)bg_me * Ssz * Hsz + jg_me;
    const float* xp_bj = g_xp + (size_t)bg_me * Msz + jg_me * 4 + g_me;
    const size_t fin_off = (size_t)Bsz * Ssz * Hsz;
    unsigned quad_off4 = (unsigned)(b_me * Hsz + jg_me) * 4u;  // quad's slot in a buffer

    __syncthreads();
    asm volatile("barrier.cluster.arrive.aligned;" ::: "memory");
    asm volatile("barrier.cluster.wait.aligned;" ::: "memory");

    for (int t = 0; t < Ssz; t++) {
        int cur = t & 3, nb = (t + 1) & 3;
        bool not_last = (t + 1 < Ssz);

        if (t) mbar_wait(my_mb + cur * 8, ((unsigned)(t - 1) >> 2) & 1u);  // full[cur]

        float acc[32];   // v = b*16 + jj*4 + g

        #pragma unroll
        for (int b = 0; b < 2; b++) {
            const float* hb = &h_s[cur][b * Hsz];
            // strided conflict-free loads: lane l -> bank l
            float hv[8];
            #pragma unroll
            for (int i = 0; i < 8; i++) hv[i] = hb[lane + 32 * i];
            ull hp[4];
            #pragma unroll
            for (int p = 0; p < 4; p++) hp[p] = pack2(hv[2 * p], hv[2 * p + 1]);

            ull acc2[16];
            #pragma unroll
            for (int m = 0; m < 16; m++) acc2[m] = 0ull;
            #pragma unroll
            for (int p = 0; p < 4; p++)
                #pragma unroll
                for (int m = 0; m < 16; m++) fma2(acc2[m], wkp[p][m], hp[p]);

            #pragma unroll
            for (int m = 0; m < 16; m++) {
                float lo, hi; unpack2(lo, hi, acc2[m]);
                acc[b * 16 + m] = lo + hi;
            }
        }

        __syncthreads();   // all warps done reading buf[cur] (ring-safety + re-arm order)

        if (tid == 0)
            mbar_expect_tx(my_mb + cur * 8, 2048);  // re-arm full[cur] (reused at t+4)

        // prefetch next xp early: DRAM latency overlaps butterfly + activation
        float xv_next = 0.f;
        if (not_last) xv_next = __ldg(xp_bj + (size_t)(t + 1) * Bsz * Msz);

        // butterfly: 32 values over 32 lanes; lane L ends with full sum of value L
        int cnt = 32;
        #pragma unroll
        for (int off = 16; off >= 1; off >>= 1) {
            cnt >>= 1;
            bool upper = (lane & off) != 0;
            #pragma unroll
            for (int v = 0; v < cnt; v++) {
                float send = upper ? acc[v] : acc[v + cnt];
                float recv = __shfl_xor_sync(0xffffffffu, send, off);
                acc[v] = (upper ? acc[v + cnt] : acc[v]) + recv;
            }
        }

        float pre = acc[0] + xv;
        float a;
        if (g_me == 2) { float e = __expf(-2.f * pre); a = __fdividef(2.f, 1.f + e) - 1.f; }
        else           { a = __fdividef(1.f, 1.f + __expf(-pre)); }

        int base = lane & ~3;
        float fg = __shfl_sync(0xffffffffu, a, base);
        float ig = __shfl_sync(0xffffffffu, a, base + 1);
        float cg = __shfl_sync(0xffffffffu, a, base + 2);
        float og = __shfl_sync(0xffffffffu, a, base + 3);

        float hn = 0.f;
        if (owner) {
            c_val = c_val * fg + ig * cg;
            float e = __expf(-2.f * c_val);
            hn = og * (__fdividef(2.f, 1.f + e) - 1.f);
        }

        // quad broadcast of hn; each lane ships it to 2 ranks (covers 0..7)
        float hn_q = __shfl_sync(0xffffffffu, hn, base);
        if (not_last) {
            unsigned off4 = (unsigned)nb * 2048u + quad_off4;
            unsigned hbits = __float_as_uint(hn_q);
            int r0 = g_me * 2;
            asm volatile(
                "st.async.weak.shared::cluster.mbarrier::complete_tx::bytes.b32 [%0], %1, [%2];"
                :: "r"(s_rh[r0] + off4), "r"(hbits),
                   "r"(s_rmb[r0] + (unsigned)nb * 8u) : "memory");
            asm volatile(
                "st.async.weak.shared::cluster.mbarrier::complete_tx::bytes.b32 [%0], %1, [%2];"
                :: "r"(s_rh[r0 + 1] + off4), "r"(hbits),
                   "r"(s_rmb[r0 + 1] + (unsigned)nb * 8u) : "memory");
        }

        // gmem output after the broadcast (off the critical chain)
        if (owner) {
            out_hj[(size_t)t * Hsz] = hn;
            if (!not_last && write_finals) {
                out[fin_off + (size_t)bg_me * Hsz + jg_me] = hn;                          // h_f
                out[fin_off + (size_t)Bsz * Hsz + (size_t)bg_me * Hsz + jg_me] = c_val;   // c_f
            }
        }
        xv = xv_next;
    }

    // lifetime safety: no CTA exits while cluster peers may have ops in flight
    asm volatile("barrier.cluster.arrive.aligned;" ::: "memory");
    asm volatile("barrier.cluster.wait.aligned;" ::: "memory");
}

// ------------------------------- launch ----------------------------------------
extern "C" void kernel_launch(void* const* d_in, const int* in_sizes, int n_in,
                              void* d_out, int out_size) {
    const float* x  = (const float*)d_in[0];
    const float* h0 = (const float*)d_in[1];
    const float* c0 = (const float*)d_in[2];
    const float* Wf = (const float*)d_in[3];
    const float* bf = (const float*)d_in[4];
    const float* Wi = (const float*)d_in[5];
    const float* bi = (const float*)d_in[6];
    const float* Wc = (const float*)d_in[7];
    const float* bc = (const float*)d_in[8];
    const float* Wo = (const float*)d_in[9];
    const float* bo = (const float*)d_in[10];
    float* out = (float*)d_out;

    int full = Bsz * Ssz * Hsz + 2 * Bsz * Hsz;
    int write_finals = (out_size >= full) ? 1 : 0;

    dim3 grid_x(8, 512);
    xproj_kernel<<<grid_x, 256>>>(x, Wf, Wi, Wc, Wo, bf, bi, bc, bo);

    lstm_rec<<<128, 256>>>(h0, c0, Wf, Wi, Wc, Wo, out, write_finals);
}

// round 17
// speedup vs baseline: 1.6671x; 1.0094x over previous
#include <cuda_runtime.h>
#include <math.h>
#include <stdint.h>

#define Bsz 32
#define Ssz 2048
#define Isz 256
#define Hsz 256
#define Msz 1024   // 4*H, packed as m = j*4 + g  (g: 0=f,1=i,2=c,3=o)

typedef unsigned long long ull;

// ------------------------------- f32x2 helpers ---------------------------------
__device__ __forceinline__ ull pack2(float lo, float hi) {
    ull r; asm("mov.b64 %0, {%1,%2};" : "=l"(r) : "f"(lo), "f"(hi)); return r;
}
__device__ __forceinline__ void unpack2(float& lo, float& hi, ull v) {
    asm("mov.b64 {%0,%1}, %2;" : "=f"(lo), "=f"(hi) : "l"(v));
}
__device__ __forceinline__ void fma2(ull& d, ull a, ull b) {
    asm("fma.rn.f32x2 %0, %1, %2, %0;" : "+l"(d) : "l"(a), "l"(b));
}
__device__ __forceinline__ ull add2(ull a, ull b) {
    ull r; asm("add.rn.f32x2 %0, %1, %2;" : "=l"(r) : "l"(a), "l"(b)); return r;
}

// ------------------------------- mbarrier helpers ------------------------------
__device__ __forceinline__ void mbar_init(unsigned addr, unsigned count) {
    asm volatile("mbarrier.init.shared.b64 [%0], %1;" :: "r"(addr), "r"(count) : "memory");
}
__device__ __forceinline__ void mbar_expect_tx(unsigned addr, unsigned bytes) {
    asm volatile("mbarrier.arrive.expect_tx.shared.b64 _, [%0], %1;"
                 :: "r"(addr), "r"(bytes) : "memory");
}
__device__ __forceinline__ void mbar_wait(unsigned addr, unsigned parity) {
    unsigned done;
    asm volatile(
        "{\n\t.reg .pred p;\n\t"
        "mbarrier.try_wait.parity.acquire.cta.shared::cta.b64 p, [%1], %2;\n\t"
        "selp.b32 %0, 1, 0, p;\n\t}"
        : "=r"(done) : "r"(addr), "r"(parity) : "memory");
    if (!done) {
        asm volatile(
            "{\n\t.reg .pred P1;\n\t"
            "WL_%=:\n\t"
            "mbarrier.try_wait.parity.acquire.cta.shared::cta.b64 P1, [%0], %1, 0x989680;\n\t"
            "@P1 bra.uni WD_%=;\n\t"
            "bra.uni WL_%=;\n\t"
            "WD_%=:\n\t}"
            :: "r"(addr), "r"(parity) : "memory");
    }
}

// ------------------------------- device scratch -------------------------------
__device__ float g_xp[(size_t)Bsz * Ssz * Msz];        // [t][b][m]  (256 MB)

// ------------------------------- xproj GEMM (f32x2, inline pack, prefetch) -----
// xp[r][m] = sum_k x_row(r)[k] * Wall[k+256][m] + b_all[m],  r = t*32 + b,
// m = j*4 + g. Software-pipelined: next tile's LDGs issue before the compute
// loop so their latency hides behind ~512 cyc of FMA.
#define XBM 128
#define XBN 128
#define XBK 8

__global__ __launch_bounds__(256) void xproj_kernel(
        const float* __restrict__ x,
        const float* __restrict__ Wf, const float* __restrict__ Wi,
        const float* __restrict__ Wc, const float* __restrict__ Wo,
        const float* __restrict__ bf, const float* __restrict__ bi,
        const float* __restrict__ bc, const float* __restrict__ bo) {
    __shared__ float As[XBK][XBM + 4];
    __shared__ float Bs[XBK][XBN];

    int bn = blockIdx.x;               // 0..7    (m blocks)
    int bm = blockIdx.y;               // 0..511  (row blocks)
    int tid = threadIdx.x;
    int tx = tid & 15;
    int ty = tid >> 4;

    int r0 = bm * XBM;
    int m0 = bn * XBN;

    int arow = tid >> 1, akq = tid & 1;
    int r = r0 + arow;
    int b = r & 31, t = r >> 5;
    const float* arow_ptr = x + ((size_t)b * Ssz + t) * Isz;

    int bk = tid >> 5, bmq = tid & 31;          // B tile: k row bk, j = bn*32+bmq
    int jb = bn * 32 + bmq;

    ull acc2[8][4];
    #pragma unroll
    for (int i = 0; i < 8; i++)
        #pragma unroll
        for (int jp = 0; jp < 4; jp++) acc2[i][jp] = 0ull;

    // prologue: tile 0 loads
    float4 a_reg = *(const float4*)(arow_ptr + akq * 4);
    float4 b_reg;
    {
        size_t off = (size_t)(bk + 256) * Hsz + jb;
        b_reg.x = Wf[off]; b_reg.y = Wi[off]; b_reg.z = Wc[off]; b_reg.w = Wo[off];
    }

    for (int k0 = 0; k0 < Isz; k0 += XBK) {
        As[akq * 4 + 0][arow] = a_reg.x;
        As[akq * 4 + 1][arow] = a_reg.y;
        As[akq * 4 + 2][arow] = a_reg.z;
        As[akq * 4 + 3][arow] = a_reg.w;
        *(float4*)&Bs[bk][bmq * 4] = b_reg;
        __syncthreads();

        // issue next tile's loads BEFORE compute (latency hidden by the FMAs)
        if (k0 + XBK < Isz) {
            a_reg = *(const float4*)(arow_ptr + k0 + XBK + akq * 4);
            size_t off = (size_t)(k0 + XBK + bk + 256) * Hsz + jb;
            b_reg.x = Wf[off]; b_reg.y = Wi[off]; b_reg.z = Wc[off]; b_reg.w = Wo[off];
        }

        #pragma unroll
        for (int kk = 0; kk < XBK; kk++) {
            float4 aA = *(float4*)&As[kk][ty * 8];
            float4 aB = *(float4*)&As[kk][ty * 8 + 4];
            ulonglong2 bL = *(ulonglong2*)&Bs[kk][tx * 8];
            ulonglong2 bH = *(ulonglong2*)&Bs[kk][tx * 8 + 4];
            ull b2[4] = {bL.x, bL.y, bH.x, bH.y};
            float ar[8] = {aA.x, aA.y, aA.z, aA.w, aB.x, aB.y, aB.z, aB.w};
            #pragma unroll
            for (int i = 0; i < 8; i++) {
                ull a2 = pack2(ar[i], ar[i]);
                #pragma unroll
                for (int jp = 0; jp < 4; jp++) fma2(acc2[i][jp], a2, b2[jp]);
            }
        }
        __syncthreads();
    }

    ull bias2[4];
    {
        int j0 = bn * 32 + tx * 2;
        bias2[0] = pack2(bf[j0], bi[j0]);
        bias2[1] = pack2(bc[j0], bo[j0]);
        bias2[2] = pack2(bf[j0 + 1], bi[j0 + 1]);
        bias2[3] = pack2(bc[j0 + 1], bo[j0 + 1]);
    }
    #pragma unroll
    for (int i = 0; i < 8; i++) {
        int rr = r0 + ty * 8 + i;
        float* dst = g_xp + (size_t)rr * Msz + m0 + tx * 8;
        ulonglong2 oL, oH;
        oL.x = add2(acc2[i][0], bias2[0]);
        oL.y = add2(acc2[i][1], bias2[1]);
        oH.x = add2(acc2[i][2], bias2[2]);
        oH.y = add2(acc2[i][3], bias2[3]);
        *(ulonglong2*)dst = oL;
        *(ulonglong2*)(dst + 4) = oH;
    }
}

// ------------------------------- clustered recurrence --------------------------
// 16 clusters x 8 CTAs x 256 threads. R16 winner (full barriers only, quad-
// spread 4B st.async sends, 4-deep ring) with the per-step __syncthreads
// REMOVED: reads-before-overwrite holds per-warp (each warp's t+2 sends follow
// its t reads in program order, and peers' t+3 stores require our full t+2
// 2048B), and the tid0 expect_tx re-arm (moved right after the full-wait)
// precedes the earliest arrival for its phase by the same transitivity.
__global__ __launch_bounds__(256, 1) __cluster_dims__(8, 1, 1)
void lstm_rec(const float* __restrict__ h0, const float* __restrict__ c0,
              const float* __restrict__ Wf, const float* __restrict__ Wi,
              const float* __restrict__ Wc, const float* __restrict__ Wo,
              float* __restrict__ out, int write_finals) {
    __shared__ __align__(16) float h_s[4][2 * Hsz];     // [buf][b_local*256 + j]
    __shared__ __align__(8) ull mbar[4];                // full[0..3]
    __shared__ unsigned s_rh[8], s_rmb[8];              // remote bases per rank

    int tid = threadIdx.x;
    int clu = blockIdx.x >> 3;
    int w = tid >> 5;
    int lane = tid & 31;
    unsigned rank;
    asm("mov.u32 %0, %%cluster_ctarank;" : "=r"(rank));

    unsigned my_hs = (unsigned)__cvta_generic_to_shared(h_s);
    unsigned my_mb = (unsigned)__cvta_generic_to_shared(mbar);
    // full[p] at my_mb + p*8

    if (tid == 0) {
        #pragma unroll
        for (int p = 0; p < 4; p++) mbar_init(my_mb + p * 8, 1);
        // pre-arm full[1..3] for stores during steps 0,1,2 (buf0 armed in-loop at t=0)
        mbar_expect_tx(my_mb + 8, 2048);
        mbar_expect_tx(my_mb + 16, 2048);
        mbar_expect_tx(my_mb + 24, 2048);
    }
    if (tid < 8) {
        unsigned a;
        asm("mapa.shared::cluster.u32 %0, %1, %2;" : "=r"(a) : "r"(my_hs), "r"(tid));
        s_rh[tid] = a;
        asm("mapa.shared::cluster.u32 %0, %1, %2;" : "=r"(a) : "r"(my_mb), "r"(tid));
        s_rmb[tid] = a;
    }

    int jg0 = (int)rank * 32 + w * 4;   // first of this warp's FOUR global j's

    // weights inline-gathered, k-pair packed over strided k:
    // wkp[p][jj*4+g] = (W_g[(lane+64p)*256 + j], W_g[(lane+64p+32)*256 + j])
    ull wkp[4][16];
    {
        const float* Wg[4] = {Wf, Wi, Wc, Wo};
        #pragma unroll
        for (int p = 0; p < 4; p++) {
            int kA = lane + 64 * p;
            int kB = kA + 32;
            #pragma unroll
            for (int jj = 0; jj < 4; jj++) {
                int j = jg0 + jj;
                #pragma unroll
                for (int g = 0; g < 4; g++)
                    wkp[p][jj * 4 + g] = pack2(Wg[g][(size_t)kA * Hsz + j],
                                               Wg[g][(size_t)kB * Hsz + j]);
            }
        }
    }

    // lane's value id: v = lane = b*16 + jj*4 + g
    int b_me = lane >> 4;
    int jj_me = (lane >> 2) & 3;
    int g_me = lane & 3;
    int jg_me = jg0 + jj_me;
    int bg_me = clu * 2 + b_me;
    bool owner = (g_me == 0);           // 8 owners per warp

    // init h0 into buf 0 (local copy: 2 batches x 256 j), 2 entries per thread
    {
        int i0 = tid, i1 = tid + 256;
        h_s[0][i0] = h0[(clu * 2 + (i0 >> 8)) * Hsz + (i0 & 255)];
        h_s[0][i1] = h0[(clu * 2 + (i1 >> 8)) * Hsz + (i1 & 255)];
    }
    float c_val = owner ? c0[bg_me * Hsz + jg_me] : 0.f;
    float xv = g_xp[(size_t)bg_me * Msz + jg_me * 4 + g_me];   // t=0

    float* out_hj = out + (size_t)bg_me * Ssz * Hsz + jg_me;
    const float* xp_bj = g_xp + (size_t)bg_me * Msz + jg_me * 4 + g_me;
    const size_t fin_off = (size_t)Bsz * Ssz * Hsz;
    unsigned quad_off4 = (unsigned)(b_me * Hsz + jg_me) * 4u;  // quad's slot in a buffer

    __syncthreads();
    asm volatile("barrier.cluster.arrive.aligned;" ::: "memory");
    asm volatile("barrier.cluster.wait.aligned;" ::: "memory");

    for (int t = 0; t < Ssz; t++) {
        int cur = t & 3, nb = (t + 1) & 3;
        bool not_last = (t + 1 < Ssz);

        if (t) mbar_wait(my_mb + cur * 8, ((unsigned)(t - 1) >> 2) & 1u);  // full[cur]

        // re-arm full[cur] for reuse at t+4 (arm precedes earliest arrival: peers'
        // t+3 sends need warp0's t+2 sends, which follow this in program order)
        if (tid == 0) mbar_expect_tx(my_mb + cur * 8, 2048);

        float acc[32];   // v = b*16 + jj*4 + g

        #pragma unroll
        for (int b = 0; b < 2; b++) {
            const float* hb = &h_s[cur][b * Hsz];
            // strided conflict-free loads: lane l -> bank l
            float hv[8];
            #pragma unroll
            for (int i = 0; i < 8; i++) hv[i] = hb[lane + 32 * i];
            ull hp[4];
            #pragma unroll
            for (int p = 0; p < 4; p++) hp[p] = pack2(hv[2 * p], hv[2 * p + 1]);

            ull acc2[16];
            #pragma unroll
            for (int m = 0; m < 16; m++) acc2[m] = 0ull;
            #pragma unroll
            for (int p = 0; p < 4; p++)
                #pragma unroll
                for (int m = 0; m < 16; m++) fma2(acc2[m], wkp[p][m], hp[p]);

            #pragma unroll
            for (int m = 0; m < 16; m++) {
                float lo, hi; unpack2(lo, hi, acc2[m]);
                acc[b * 16 + m] = lo + hi;
            }
        }

        // prefetch next xp early: DRAM latency overlaps butterfly + activation
        float xv_next = 0.f;
        if (not_last) xv_next = __ldg(xp_bj + (size_t)(t + 1) * Bsz * Msz);

        // butterfly: 32 values over 32 lanes; lane L ends with full sum of value L
        int cnt = 32;
        #pragma unroll
        for (int off = 16; off >= 1; off >>= 1) {
            cnt >>= 1;
            bool upper = (lane & off) != 0;
            #pragma unroll
            for (int v = 0; v < cnt; v++) {
                float send = upper ? acc[v] : acc[v + cnt];
                float recv = __shfl_xor_sync(0xffffffffu, send, off);
                acc[v] = (upper ? acc[v + cnt] : acc[v]) + recv;
            }
        }

        float pre = acc[0] + xv;
        float a;
        if (g_me == 2) { float e = __expf(-2.f * pre); a = __fdividef(2.f, 1.f + e) - 1.f; }
        else           { a = __fdividef(1.f, 1.f + __expf(-pre)); }

        int base = lane & ~3;
        float fg = __shfl_sync(0xffffffffu, a, base);
        float ig = __shfl_sync(0xffffffffu, a, base + 1);
        float cg = __shfl_sync(0xffffffffu, a, base + 2);
        float og = __shfl_sync(0xffffffffu, a, base + 3);

        float hn = 0.f;
        if (owner) {
            c_val = c_val * fg + ig * cg;
            float e = __expf(-2.f * c_val);
            hn = og * (__fdividef(2.f, 1.f + e) - 1.f);
        }

        // quad broadcast of hn; each lane ships it to 2 ranks (covers 0..7)
        float hn_q = __shfl_sync(0xffffffffu, hn, base);
        if (not_last) {
            unsigned off4 = (unsigned)nb * 2048u + quad_off4;
            unsigned hbits = __float_as_uint(hn_q);
            int r0 = g_me * 2;
            asm volatile(
                "st.async.weak.shared::cluster.mbarrier::complete_tx::bytes.b32 [%0], %1, [%2];"
                :: "r"(s_rh[r0] + off4), "r"(hbits),
                   "r"(s_rmb[r0] + (unsigned)nb * 8u) : "memory");
            asm volatile(
                "st.async.weak.shared::cluster.mbarrier::complete_tx::bytes.b32 [%0], %1, [%2];"
                :: "r"(s_rh[r0 + 1] + off4), "r"(hbits),
                   "r"(s_rmb[r0 + 1] + (unsigned)nb * 8u) : "memory");
        }

        // gmem output after the broadcast (off the critical chain)
        if (owner) {
            out_hj[(size_t)t * Hsz] = hn;
            if (!not_last && write_finals) {
                out[fin_off + (size_t)bg_me * Hsz + jg_me] = hn;                          // h_f
                out[fin_off + (size_t)Bsz * Hsz + (size_t)bg_me * Hsz + jg_me] = c_val;   // c_f
            }
        }
        xv = xv_next;
    }

    // lifetime safety: no CTA exits while cluster peers may have ops in flight
    asm volatile("barrier.cluster.arrive.aligned;" ::: "memory");
    asm volatile("barrier.cluster.wait.aligned;" ::: "memory");
}

// ------------------------------- launch ----------------------------------------
extern "C" void kernel_launch(void* const* d_in, const int* in_sizes, int n_in,
                              void* d_out, int out_size) {
    const float* x  = (const float*)d_in[0];
    const float* h0 = (const float*)d_in[1];
    const float* c0 = (const float*)d_in[2];
    const float* Wf = (const float*)d_in[3];
    const float* bf = (const float*)d_in[4];
    const float* Wi = (const float*)d_in[5];
    const float* bi = (const float*)d_in[6];
    const float* Wc = (const float*)d_in[7];
    const float* bc = (const float*)d_in[8];
    const float* Wo = (const float*)d_in[9];
    const float* bo = (const float*)d_in[10];
    float* out = (float*)d_out;

    int full = Bsz * Ssz * Hsz + 2 * Bsz * Hsz;
    int write_finals = (out_size >= full) ? 1 : 0;

    dim3 grid_x(8, 512);
    xproj_kernel<<<grid_x, 256>>>(x, Wf, Wi, Wc, Wo, bf, bi, bc, bo);

    lstm_rec<<<128, 256>>>(h0, c0, Wf, Wi, Wc, Wo, out, write_finals);
}